// round 1
// baseline (speedup 1.0000x reference)
#include <cuda_runtime.h>
#include <math.h>
#include <stdint.h>

// ---------------- constants ----------------
#define NB1   64          // kernel1 blocks (must be <= #SMs, all co-resident)
#define NT1   256         // kernel1 threads per block (8 warps)
#define NBD   592         // decoder blocks
#define NTD   256         // decoder threads

#define HC    256
#define HW    512
#define VOC   50000
#define LCH   12

// d_out layout: [y(50000) | h_word_h(1024) | h_word_c(1024) | h_char_h(512) | h_char_c(512)]
#define OUT_Y   0
#define OUT_WH  50000
#define OUT_WC  51024
#define OUT_CH  52048
#define OUT_CC  52560

// ---------------- device-global scratch (no allocs allowed) ----------------
__device__ float g_h0[2][HC];      // char layer0 hidden, ping-pong
__device__ float g_h1[2][HC];      // char layer1 hidden, ping-pong
__device__ float g_c1buf[HC];      // final layer1 cell state
__device__ float g_xc[HW];         // char_to_embedding @ c1
__device__ float g_gateval;        // scalar gate g
__device__ float g_wh[HW];         // word layer0 hidden
__device__ float g_y[HW];          // word layer1 hidden (decoder input)
__device__ unsigned g_bar_count = 0;
__device__ volatile unsigned g_bar_gen = 0;

// ---------------- helpers ----------------
__device__ __forceinline__ void gbar() {
    __syncthreads();
    if (threadIdx.x == 0) {
        unsigned gen = g_bar_gen;
        __threadfence();
        if (atomicAdd(&g_bar_count, 1u) == NB1 - 1) {
            g_bar_count = 0;
            __threadfence();
            g_bar_gen = gen + 1;
        } else {
            while (g_bar_gen == gen) { }
        }
    }
    __syncthreads();
}

__device__ __forceinline__ float warp_sum(float v) {
#pragma unroll
    for (int o = 16; o > 0; o >>= 1) v += __shfl_xor_sync(0xffffffffu, v, o);
    return v;
}
__device__ __forceinline__ float sigf(float x) { return 1.f / (1.f + expf(-x)); }
__device__ __forceinline__ float vload(const float* p) { return *(volatile const float*)p; }
__device__ __forceinline__ void  vstore(float* p, float v) { *(volatile float*)p = v; }

// ---------------- kernel 1: char LSTM + gate + word LSTM (persistent) ----------------
__global__ void __launch_bounds__(NT1, 1) k_main(
    const int*   x_word,   const int*   x_char,
    const float* h_word_h, const float* h_word_c,
    const float* h_char_h, const float* h_char_c,
    const float* word_emb, const float* word_Wih, const float* word_Whh,
    const float* word_bih, const float* word_bhh,
    const float* char_emb, const float* char_Wih, const float* char_Whh,
    const float* char_bih, const float* char_bhh,
    const float* c2e,      const float* gw_vec,   const float* gb_scal,
    float* out)
{
    const int lane = threadIdx.x & 31;
    const int wid  = threadIdx.x >> 5;
    const int gw   = blockIdx.x * (NT1 / 32) + wid;   // global warp id, 0..511

    __shared__ int sx[LCH];
    if (threadIdx.x < LCH) sx[threadIdx.x] = x_char[threadIdx.x];
    __syncthreads();

    // ---------- char phase: warp gw (<256) owns element j for BOTH layers ----------
    float wih[2][4][8], whh[2][4][8];   // 128 register-resident weight floats / lane
    float bias[2][4];
    float c0 = 0.f, c1 = 0.f, h0l = 0.f, h1l = 0.f;
    const int j = gw;

    if (gw < HC) {
#pragma unroll
        for (int l = 0; l < 2; l++) {
#pragma unroll
            for (int q = 0; q < 4; q++) {
                int row = l * (4 * HC) + q * HC + j;
                const float* pi = char_Wih + (size_t)row * HC + lane;
                const float* ph = char_Whh + (size_t)row * HC + lane;
#pragma unroll
                for (int u = 0; u < 8; u++) {
                    wih[l][q][u] = pi[32 * u];
                    whh[l][q][u] = ph[32 * u];
                }
                bias[l][q] = char_bih[row] + char_bhh[row];
            }
        }
        c0 = h_char_c[j];
        c1 = h_char_c[HC + j];
        if (lane == 0) {
            vstore(&g_h0[0][j], h_char_h[j]);
            vstore(&g_h1[0][j], h_char_h[HC + j]);
        }
    }
    gbar();

#pragma unroll 1
    for (int t = 0; t < LCH; t++) {
        const int rp = t & 1, wp = rp ^ 1;
        // ---- layer 0 ----
        if (gw < HC) {
            const int ci = sx[t];
            const float* ce = char_emb + (size_t)ci * HC + lane;
            float xv[8], hv[8];
#pragma unroll
            for (int u = 0; u < 8; u++) {
                xv[u] = ce[32 * u];
                hv[u] = vload(&g_h0[rp][lane + 32 * u]);
            }
            float acc[4];
#pragma unroll
            for (int q = 0; q < 4; q++) {
                float a = 0.f;
#pragma unroll
                for (int u = 0; u < 8; u++)
                    a += wih[0][q][u] * xv[u] + whh[0][q][u] * hv[u];
                acc[q] = warp_sum(a) + bias[0][q];
            }
            float ig = sigf(acc[0]), fg = sigf(acc[1]);
            float gg = tanhf(acc[2]), og = sigf(acc[3]);
            c0  = fg * c0 + ig * gg;
            h0l = og * tanhf(c0);
            if (lane == 0) vstore(&g_h0[wp][j], h0l);
        }
        gbar();
        // ---- layer 1 ----
        if (gw < HC) {
            float xv[8], hv[8];
#pragma unroll
            for (int u = 0; u < 8; u++) {
                xv[u] = vload(&g_h0[wp][lane + 32 * u]);   // current layer0 output
                hv[u] = vload(&g_h1[rp][lane + 32 * u]);
            }
            float acc[4];
#pragma unroll
            for (int q = 0; q < 4; q++) {
                float a = 0.f;
#pragma unroll
                for (int u = 0; u < 8; u++)
                    a += wih[1][q][u] * xv[u] + whh[1][q][u] * hv[u];
                acc[q] = warp_sum(a) + bias[1][q];
            }
            float ig = sigf(acc[0]), fg = sigf(acc[1]);
            float gg = tanhf(acc[2]), og = sigf(acc[3]);
            c1  = fg * c1 + ig * gg;
            h1l = og * tanhf(c1);
            if (lane == 0) {
                vstore(&g_h1[wp][j], h1l);
                if (t == LCH - 1) {
                    vstore(&g_c1buf[j], c1);
                    out[OUT_CH + j]      = h0l;
                    out[OUT_CH + HC + j] = h1l;
                    out[OUT_CC + j]      = c0;
                    out[OUT_CC + HC + j] = c1;
                }
            }
        }
        gbar();
    }

    // ---------- phase A: x_c = c2e @ c1  (512 rows, one per warp) and gate ----------
    {
        const int row = gw;   // 0..511
        const float* pr = c2e + (size_t)row * HC + lane;
        float a = 0.f;
#pragma unroll
        for (int u = 0; u < 8; u++)
            a += pr[32 * u] * vload(&g_c1buf[lane + 32 * u]);
        a = warp_sum(a);
        if (lane == 0) vstore(&g_xc[row], a);

        if (gw == 0) {
            const int widx = x_word[0];
            const float* we = word_emb + (size_t)widx * HW + lane;
            const float* gp = gw_vec + lane;
            float s = 0.f;
#pragma unroll
            for (int u = 0; u < 16; u++) s += gp[32 * u] * we[32 * u];
            s = warp_sum(s) + gb_scal[0];
            if (lane == 0) vstore(&g_gateval, fmaxf(s, 0.f));
        }
    }
    gbar();

    // ---------- word LSTM: 512 elements, warp per element ----------
    const float gval = vload(&g_gateval);
    const int   widx = x_word[0];
    const int   e    = gw;    // 0..511

    // ---- layer 0 ----
    {
        const float4* we4 = (const float4*)(word_emb + (size_t)widx * HW);
        const float4* hh4 = (const float4*)(h_word_h);
        float4 xv4[4], hv4[4];
#pragma unroll
        for (int u = 0; u < 4; u++) {
            const int k4 = lane + 32 * u;
            float4 xw = we4[k4];
            float x0 = vload(&g_xc[4 * k4 + 0]);
            float x1 = vload(&g_xc[4 * k4 + 1]);
            float x2 = vload(&g_xc[4 * k4 + 2]);
            float x3 = vload(&g_xc[4 * k4 + 3]);
            xv4[u].x = (1.f - gval) * xw.x + gval * x0;
            xv4[u].y = (1.f - gval) * xw.y + gval * x1;
            xv4[u].z = (1.f - gval) * xw.z + gval * x2;
            xv4[u].w = (1.f - gval) * xw.w + gval * x3;
            hv4[u] = hh4[k4];
        }
        float acc[4];
#pragma unroll
        for (int q = 0; q < 4; q++) {
            const int row = q * HW + e;
            const float4* wi = (const float4*)(word_Wih + (size_t)row * HW);
            const float4* wh = (const float4*)(word_Whh + (size_t)row * HW);
            float a = 0.f;
#pragma unroll
            for (int u = 0; u < 4; u++) {
                const int k4 = lane + 32 * u;
                float4 wiv = wi[k4], whv = wh[k4];
                a += wiv.x * xv4[u].x + wiv.y * xv4[u].y + wiv.z * xv4[u].z + wiv.w * xv4[u].w;
                a += whv.x * hv4[u].x + whv.y * hv4[u].y + whv.z * hv4[u].z + whv.w * hv4[u].w;
            }
            acc[q] = warp_sum(a) + word_bih[row] + word_bhh[row];
        }
        float ig = sigf(acc[0]), fg = sigf(acc[1]);
        float gg = tanhf(acc[2]), og = sigf(acc[3]);
        float cw = fg * h_word_c[e] + ig * gg;
        float hw = og * tanhf(cw);
        if (lane == 0) {
            vstore(&g_wh[e], hw);
            out[OUT_WH + e] = hw;
            out[OUT_WC + e] = cw;
        }
    }
    gbar();

    // ---- layer 1 ----
    {
        const float4* hh4 = (const float4*)(h_word_h + HW);
        float4 xv4[4], hv4[4];
#pragma unroll
        for (int u = 0; u < 4; u++) {
            const int k4 = lane + 32 * u;
            xv4[u].x = vload(&g_wh[4 * k4 + 0]);
            xv4[u].y = vload(&g_wh[4 * k4 + 1]);
            xv4[u].z = vload(&g_wh[4 * k4 + 2]);
            xv4[u].w = vload(&g_wh[4 * k4 + 3]);
            hv4[u] = hh4[k4];
        }
        float acc[4];
#pragma unroll
        for (int q = 0; q < 4; q++) {
            const int row = 4 * HW + q * HW + e;   // layer1 offset = 2048 rows
            const float4* wi = (const float4*)(word_Wih + (size_t)row * HW);
            const float4* wh = (const float4*)(word_Whh + (size_t)row * HW);
            float a = 0.f;
#pragma unroll
            for (int u = 0; u < 4; u++) {
                const int k4 = lane + 32 * u;
                float4 wiv = wi[k4], whv = wh[k4];
                a += wiv.x * xv4[u].x + wiv.y * xv4[u].y + wiv.z * xv4[u].z + wiv.w * xv4[u].w;
                a += whv.x * hv4[u].x + whv.y * hv4[u].y + whv.z * hv4[u].z + whv.w * hv4[u].w;
            }
            acc[q] = warp_sum(a) + word_bih[row] + word_bhh[row];
        }
        float ig = sigf(acc[0]), fg = sigf(acc[1]);
        float gg = tanhf(acc[2]), og = sigf(acc[3]);
        float cw = fg * h_word_c[HW + e] + ig * gg;
        float hw = og * tanhf(cw);
        if (lane == 0) {
            vstore(&g_y[e], hw);
            out[OUT_WH + HW + e] = hw;
            out[OUT_WC + HW + e] = cw;
        }
    }
    // kernel boundary provides ordering for the decoder kernel
}

// ---------------- kernel 2: decoder GEMV (50000 x 512), HBM-bound ----------------
__global__ void __launch_bounds__(NTD) k_dec(const float* __restrict__ dec_W,
                                             const float* __restrict__ dec_b,
                                             float* __restrict__ out)
{
    __shared__ float ys[HW];
    for (int i = threadIdx.x; i < HW; i += NTD) ys[i] = vload(&g_y[i]);
    __syncthreads();

    const int lane = threadIdx.x & 31;
    const int wid  = threadIdx.x >> 5;
    const int gw   = blockIdx.x * (NTD / 32) + wid;
    const int nwarps = NBD * (NTD / 32);

    const float4* y4 = (const float4*)ys;
    float4 yv[4];
#pragma unroll
    for (int u = 0; u < 4; u++) yv[u] = y4[lane + 32 * u];

    for (int row = gw; row < VOC; row += nwarps) {
        const float4* w = (const float4*)(dec_W + (size_t)row * HW);
        float a = 0.f;
#pragma unroll
        for (int u = 0; u < 4; u++) {
            float4 wv = w[lane + 32 * u];
            a += wv.x * yv[u].x + wv.y * yv[u].y + wv.z * yv[u].z + wv.w * yv[u].w;
        }
        a = warp_sum(a);
        if (lane == 0) out[row] = a + dec_b[row];
    }
}

// ---------------- launch ----------------
extern "C" void kernel_launch(void* const* d_in, const int* in_sizes, int n_in,
                              void* d_out, int out_size)
{
    (void)in_sizes; (void)n_in; (void)out_size;
    const int*   x_word   = (const int*)  d_in[0];
    const int*   x_char   = (const int*)  d_in[1];
    const float* h_word_h = (const float*)d_in[2];
    const float* h_word_c = (const float*)d_in[3];
    const float* h_char_h = (const float*)d_in[4];
    const float* h_char_c = (const float*)d_in[5];
    const float* word_emb = (const float*)d_in[6];
    const float* word_Wih = (const float*)d_in[7];
    const float* word_Whh = (const float*)d_in[8];
    const float* word_bih = (const float*)d_in[9];
    const float* word_bhh = (const float*)d_in[10];
    const float* dec_W    = (const float*)d_in[11];
    const float* dec_b    = (const float*)d_in[12];
    const float* char_emb = (const float*)d_in[13];
    const float* char_Wih = (const float*)d_in[14];
    const float* char_Whh = (const float*)d_in[15];
    const float* char_bih = (const float*)d_in[16];
    const float* char_bhh = (const float*)d_in[17];
    const float* c2e      = (const float*)d_in[18];
    const float* g_w      = (const float*)d_in[19];
    const float* g_b      = (const float*)d_in[20];
    float* out = (float*)d_out;

    k_main<<<NB1, NT1>>>(x_word, x_char, h_word_h, h_word_c, h_char_h, h_char_c,
                         word_emb, word_Wih, word_Whh, word_bih, word_bhh,
                         char_emb, char_Wih, char_Whh, char_bih, char_bhh,
                         c2e, g_w, g_b, out);
    k_dec<<<NBD, NTD>>>(dec_W, dec_b, out);
}

// round 2
// speedup vs baseline: 1.4500x; 1.4500x over previous
#include <cuda_runtime.h>
#include <math.h>
#include <stdint.h>

// ---------------- constants ----------------
#define NB1   64          // k_char blocks (all co-resident; 1 CTA/SM)
#define NT1   256
#define NBW   128         // k_word blocks
#define NTW   128
#define NBD   3125        // decoder blocks: 3125*8 warps * 2 rows = 50000
#define NTD   256

#define HC    256
#define HW    512
#define VOC   50000
#define LCH   12

// d_out layout: [y(50000) | h_word_h(1024) | h_word_c(1024) | h_char_h(512) | h_char_c(512)]
#define OUT_WH  50000
#define OUT_WC  51024
#define OUT_CH  52048
#define OUT_CC  52560

// ---------------- device-global scratch ----------------
__device__ float g_h0[2][HC];      // char layer0 hidden ping-pong
__device__ float g_h1[2][HC];      // char layer1 hidden ping-pong
__device__ float g_c1[HC];         // final layer1 cell
__device__ float g_xc[HW];         // char_to_embedding @ c1
__device__ float g_gate;           // scalar gate
__device__ float g_wh[HW];         // word layer0 hidden
__device__ float g_y[HW];          // word layer1 hidden (decoder input)
__device__ unsigned g_cnt = 0;
__device__ volatile unsigned g_gen = 0;

// ---------------- helpers ----------------
__device__ __forceinline__ void gbar() {
    __syncthreads();
    if (threadIdx.x == 0) {
        unsigned gen = g_gen;
        __threadfence();
        if (atomicAdd(&g_cnt, 1u) == NB1 - 1) {
            g_cnt = 0;
            __threadfence();
            g_gen = gen + 1;
        } else {
            while (g_gen == gen) { }
        }
    }
    __syncthreads();
}

__device__ __forceinline__ float warp_sum(float v) {
#pragma unroll
    for (int o = 16; o > 0; o >>= 1) v += __shfl_xor_sync(0xffffffffu, v, o);
    return v;
}
// fast activations via MUFU.EX2 (rel err ~1e-7, tolerance is 1e-3)
__device__ __forceinline__ float fsig(float x)  { return __fdividef(1.f, 1.f + __expf(-x)); }
__device__ __forceinline__ float ftanh(float x) { float e = __expf(2.f * x); return 1.f - __fdividef(2.f, e + 1.f); }
__device__ __forceinline__ float dot4(float4 a, float4 b) {
    return a.x * b.x + a.y * b.y + a.z * b.z + a.w * b.w;
}

// ============ kernel 1: char LSTM (pipelined layers) + xc + gate ============
__global__ void __launch_bounds__(NT1, 1) k_char(
    const int*   x_word,   const int*   x_char,
    const float* h_char_h, const float* h_char_c,
    const float* char_emb, const float* char_Wih, const float* char_Whh,
    const float* char_bih, const float* char_bhh,
    const float* c2e,      const float* word_emb,
    const float* gw_vec,   const float* gb_scal,
    float* out)
{
    const int lane  = threadIdx.x & 31;
    const int wid   = threadIdx.x >> 5;
    const int gw    = blockIdx.x * (NT1 / 32) + wid;   // 0..511
    const int layer = (gw >= HC) ? 1 : 0;
    const int j     = layer ? (gw - HC) : gw;          // owned hidden element

    __shared__ int sx[LCH];
    if (threadIdx.x < LCH) sx[threadIdx.x] = x_char[threadIdx.x];
    __syncthreads();

    // register-resident weights for (element j, layer)
    float4 wi[4][2], wh[4][2];
    float  bias[4];
#pragma unroll
    for (int q = 0; q < 4; q++) {
        const int row = layer * (4 * HC) + q * HC + j;
        const float4* pi = (const float4*)(char_Wih + (size_t)row * HC);
        const float4* ph = (const float4*)(char_Whh + (size_t)row * HC);
#pragma unroll
        for (int u = 0; u < 2; u++) {
            wi[q][u] = pi[lane + 32 * u];
            wh[q][u] = ph[lane + 32 * u];
        }
        bias[q] = char_bih[row] + char_bhh[row];
    }
    float c = h_char_c[layer * HC + j];
    if (lane == 0) {
        const float h0v = h_char_h[layer * HC + j];
        if (layer == 0) __stcg(&g_h0[0][j], h0v);
        else            __stcg(&g_h1[0][j], h0v);
    }
    gbar();

    // pipelined phases: phase p runs layer0 step p and layer1 step p-1
#pragma unroll 1
    for (int p = 0; p <= LCH; p++) {
        if (layer == 0) {
            if (p < LCH) {
                const float4* xe = (const float4*)(char_emb + (size_t)sx[p] * HC);
                const float4* hb = (const float4*)g_h0[p & 1];
                const float4 x0 = xe[lane],            x1 = xe[lane + 32];
                const float4 h0 = __ldcg(hb + lane),   h1 = __ldcg(hb + lane + 32);
                float acc[4];
#pragma unroll
                for (int q = 0; q < 4; q++) {
                    float a = dot4(wi[q][0], x0) + dot4(wi[q][1], x1)
                            + dot4(wh[q][0], h0) + dot4(wh[q][1], h1);
                    acc[q] = warp_sum(a) + bias[q];
                }
                const float ig = fsig(acc[0]), fg = fsig(acc[1]);
                const float gg = ftanh(acc[2]), og = fsig(acc[3]);
                c = fg * c + ig * gg;
                const float h = og * ftanh(c);
                if (lane == 0) {
                    __stcg(&g_h0[(p + 1) & 1][j], h);
                    if (p == LCH - 1) { out[OUT_CH + j] = h; out[OUT_CC + j] = c; }
                }
            }
        } else {
            if (p >= 1) {
                const float4* xb = (const float4*)g_h0[p & 1];        // layer0 out of step p-1
                const float4* hb = (const float4*)g_h1[(p - 1) & 1];
                const float4 x0 = __ldcg(xb + lane), x1 = __ldcg(xb + lane + 32);
                const float4 h0 = __ldcg(hb + lane), h1 = __ldcg(hb + lane + 32);
                float acc[4];
#pragma unroll
                for (int q = 0; q < 4; q++) {
                    float a = dot4(wi[q][0], x0) + dot4(wi[q][1], x1)
                            + dot4(wh[q][0], h0) + dot4(wh[q][1], h1);
                    acc[q] = warp_sum(a) + bias[q];
                }
                const float ig = fsig(acc[0]), fg = fsig(acc[1]);
                const float gg = ftanh(acc[2]), og = fsig(acc[3]);
                c = fg * c + ig * gg;
                const float h = og * ftanh(c);
                if (lane == 0) {
                    __stcg(&g_h1[p & 1][j], h);
                    if (p == LCH) {
                        __stcg(&g_c1[j], c);
                        out[OUT_CH + HC + j] = h;
                        out[OUT_CC + HC + j] = c;
                    }
                }
            }
        }
        gbar();
    }

    // xc = c2e @ c1 : warp gw computes row gw (0..511); warp 0 also computes the gate
    {
        const float4* pr  = (const float4*)(c2e + (size_t)gw * HC);
        const float4* c1b = (const float4*)g_c1;
        float a = dot4(pr[lane],      __ldcg(c1b + lane))
                + dot4(pr[lane + 32], __ldcg(c1b + lane + 32));
        a = warp_sum(a);
        if (lane == 0) __stcg(&g_xc[gw], a);

        if (gw == 0) {
            const int widx = x_word[0];
            const float4* we = (const float4*)(word_emb + (size_t)widx * HW);
            const float4* gp = (const float4*)gw_vec;
            float s = 0.f;
#pragma unroll
            for (int u = 0; u < 4; u++) s += dot4(gp[lane + 32 * u], we[lane + 32 * u]);
            s = warp_sum(s) + gb_scal[0];
            if (lane == 0) __stcg(&g_gate, fmaxf(s, 0.f));
        }
    }
    // kernel boundary orders everything for k_word
}

// ============ kernel 2/3: one word-LSTM layer (full grid, warp per element) ============
__global__ void __launch_bounds__(NTW) k_word(
    const int*   x_word,
    const float* word_emb,
    const float* Wih, const float* Whh, const float* bih, const float* bhh,
    const float* h_in, const float* c_in,
    float* out, int layer)
{
    const int lane = threadIdx.x & 31;
    const int wid  = threadIdx.x >> 5;
    const int e    = blockIdx.x * (NTW / 32) + wid;    // 0..511

    float4 xv[4], hv[4];
    if (layer == 0) {
        const float g    = __ldcg(&g_gate);
        const int   widx = x_word[0];
        const float4* we = (const float4*)(word_emb + (size_t)widx * HW);
        const float4* xc = (const float4*)g_xc;
#pragma unroll
        for (int u = 0; u < 4; u++) {
            const float4 a = we[lane + 32 * u];
            const float4 b = __ldcg(xc + lane + 32 * u);
            xv[u] = make_float4((1.f - g) * a.x + g * b.x,
                                (1.f - g) * a.y + g * b.y,
                                (1.f - g) * a.z + g * b.z,
                                (1.f - g) * a.w + g * b.w);
        }
    } else {
        const float4* xb = (const float4*)g_wh;
#pragma unroll
        for (int u = 0; u < 4; u++) xv[u] = __ldcg(xb + lane + 32 * u);
    }
    const float4* hb = (const float4*)(h_in + (size_t)layer * HW);
#pragma unroll
    for (int u = 0; u < 4; u++) hv[u] = hb[lane + 32 * u];

    float acc[4];
#pragma unroll
    for (int q = 0; q < 4; q++) {
        const int row = layer * (4 * HW) + q * HW + e;
        const float4* wi = (const float4*)(Wih + (size_t)row * HW);
        const float4* wh = (const float4*)(Whh + (size_t)row * HW);
        float a = 0.f;
#pragma unroll
        for (int u = 0; u < 4; u++) {
            a += dot4(__ldcg(wi + lane + 32 * u), xv[u]);
            a += dot4(__ldcg(wh + lane + 32 * u), hv[u]);
        }
        acc[q] = warp_sum(a) + bih[row] + bhh[row];
    }
    const float ig = fsig(acc[0]), fg = fsig(acc[1]);
    const float gg = ftanh(acc[2]), og = fsig(acc[3]);
    const float cw = fg * c_in[layer * HW + e] + ig * gg;
    const float hw = og * ftanh(cw);
    if (lane == 0) {
        if (layer == 0) {
            __stcg(&g_wh[e], hw);
            out[OUT_WH + e] = hw;
            out[OUT_WC + e] = cw;
        } else {
            __stcg(&g_y[e], hw);
            out[OUT_WH + HW + e] = hw;
            out[OUT_WC + HW + e] = cw;
        }
    }
}

// ============ kernel 4: decoder GEMV (50000 x 512), 2 rows/warp ============
__global__ void __launch_bounds__(NTD) k_dec(const float* __restrict__ dec_W,
                                             const float* __restrict__ dec_b,
                                             float* __restrict__ out)
{
    __shared__ float ys[HW];
    for (int i = threadIdx.x; i < HW; i += NTD) ys[i] = __ldcg(&g_y[i]);
    __syncthreads();

    const int lane = threadIdx.x & 31;
    const int wid  = threadIdx.x >> 5;
    const int gw   = blockIdx.x * (NTD / 32) + wid;
    const int r0   = 2 * gw;                       // exact cover: 25000 warps * 2 rows

    const float4* y4 = (const float4*)ys;
    float4 yv[4];
#pragma unroll
    for (int u = 0; u < 4; u++) yv[u] = y4[lane + 32 * u];

    const float4* w0 = (const float4*)(dec_W + (size_t)r0 * HW);
    const float4* w1 = w0 + HW / 4;
    float a0 = 0.f, a1 = 0.f;
#pragma unroll
    for (int u = 0; u < 4; u++) {
        const float4 v0 = __ldcg(w0 + lane + 32 * u);
        const float4 v1 = __ldcg(w1 + lane + 32 * u);
        a0 += dot4(v0, yv[u]);
        a1 += dot4(v1, yv[u]);
    }
    a0 = warp_sum(a0);
    a1 = warp_sum(a1);
    if (lane == 0) {
        out[r0]     = a0 + dec_b[r0];
        out[r0 + 1] = a1 + dec_b[r0 + 1];
    }
}

// ---------------- launch ----------------
extern "C" void kernel_launch(void* const* d_in, const int* in_sizes, int n_in,
                              void* d_out, int out_size)
{
    (void)in_sizes; (void)n_in; (void)out_size;
    const int*   x_word   = (const int*)  d_in[0];
    const int*   x_char   = (const int*)  d_in[1];
    const float* h_word_h = (const float*)d_in[2];
    const float* h_word_c = (const float*)d_in[3];
    const float* h_char_h = (const float*)d_in[4];
    const float* h_char_c = (const float*)d_in[5];
    const float* word_emb = (const float*)d_in[6];
    const float* word_Wih = (const float*)d_in[7];
    const float* word_Whh = (const float*)d_in[8];
    const float* word_bih = (const float*)d_in[9];
    const float* word_bhh = (const float*)d_in[10];
    const float* dec_W    = (const float*)d_in[11];
    const float* dec_b    = (const float*)d_in[12];
    const float* char_emb = (const float*)d_in[13];
    const float* char_Wih = (const float*)d_in[14];
    const float* char_Whh = (const float*)d_in[15];
    const float* char_bih = (const float*)d_in[16];
    const float* char_bhh = (const float*)d_in[17];
    const float* c2e      = (const float*)d_in[18];
    const float* g_w      = (const float*)d_in[19];
    const float* g_b      = (const float*)d_in[20];
    float* out = (float*)d_out;

    k_char<<<NB1, NT1>>>(x_word, x_char, h_char_h, h_char_c,
                         char_emb, char_Wih, char_Whh, char_bih, char_bhh,
                         c2e, word_emb, g_w, g_b, out);
    k_word<<<NBW, NTW>>>(x_word, word_emb, word_Wih, word_Whh, word_bih, word_bhh,
                         h_word_h, h_word_c, out, 0);
    k_word<<<NBW, NTW>>>(x_word, word_emb, word_Wih, word_Whh, word_bih, word_bhh,
                         h_word_h, h_word_c, out, 1);
    k_dec<<<NBD, NTD>>>(dec_W, dec_b, out);
}

// round 3
// speedup vs baseline: 1.4670x; 1.0117x over previous
#include <cuda_runtime.h>
#include <math.h>
#include <stdint.h>

// ---------------- constants ----------------
#define NBF   148         // fused kernel blocks (all co-resident, 1/SM)
#define NBC   64          // of which: char/word compute CTAs
#define NT1   256
#define NBD   3125        // decoder blocks: 3125*8 warps * 2 rows = 50000
#define NTD   256

#define HC    256
#define HW    512
#define VOC   50000
#define LCH   12

// d_out layout: [y(50000) | h_word_h(1024) | h_word_c(1024) | h_char_h(512) | h_char_c(512)]
#define OUT_WH  50000
#define OUT_WC  51024
#define OUT_CH  52048
#define OUT_CC  52560

// ---------------- device-global scratch ----------------
__device__ float g_h0[2][HC];
__device__ float g_h1[2][HC];
__device__ float g_c1[HC];
__device__ float g_xc[HW];
__device__ float g_gate;
__device__ float g_wh[HW];
__device__ float g_y[HW];
__device__ unsigned g_cnt  = 0;
__device__ volatile unsigned g_gen = 0;
__device__ unsigned g_done = 0;        // monotonic across launches

// ---------------- helpers ----------------
__device__ __forceinline__ void gbar() {          // 64-CTA barrier (compute CTAs only)
    __syncthreads();
    if (threadIdx.x == 0) {
        unsigned gen = g_gen;
        __threadfence();
        if (atomicAdd(&g_cnt, 1u) == NBC - 1) {
            g_cnt = 0;
            __threadfence();
            g_gen = gen + 1;
        } else {
            while (g_gen == gen) { }
        }
    }
    __syncthreads();
}

__device__ __forceinline__ float warp_sum(float v) {
#pragma unroll
    for (int o = 16; o > 0; o >>= 1) v += __shfl_xor_sync(0xffffffffu, v, o);
    return v;
}
__device__ __forceinline__ float fsig(float x)  { return __fdividef(1.f, 1.f + __expf(-x)); }
__device__ __forceinline__ float ftanh(float x) { float e = __expf(2.f * x); return 1.f - __fdividef(2.f, e + 1.f); }
__device__ __forceinline__ float dot4(float4 a, float4 b) {
    return a.x * b.x + a.y * b.y + a.z * b.z + a.w * b.w;
}
__device__ __forceinline__ void pf_l2(const void* p) {
    asm volatile("prefetch.global.L2 [%0];" :: "l"(p));
}

// ============ fused kernel: char LSTM + gate + word LSTM  ||  L2 prefetch ============
__global__ void __launch_bounds__(NT1, 1) k_fused(
    const int*   x_word,   const int*   x_char,
    const float* h_word_h, const float* h_word_c,
    const float* h_char_h, const float* h_char_c,
    const float* word_emb, const float* word_Wih, const float* word_Whh,
    const float* word_bih, const float* word_bhh,
    const float* char_emb, const float* char_Wih, const float* char_Whh,
    const float* char_bih, const float* char_bhh,
    const float* c2e,      const float* gw_vec,   const float* gb_scal,
    const float* dec_W,
    float* out)
{
    // ---------------- prefetch CTAs ----------------
    if (blockIdx.x >= NBC) {
        const unsigned base = *(volatile unsigned*)&g_done;
        const int g   = (blockIdx.x - NBC) * NT1 + threadIdx.x;   // 0..21503
        const int NTH = (NBF - NBC) * NT1;                        // 21504

        // region 1: word weights (16 MB) — needed soonest
        const size_t n1 = (size_t)2 * 2048 * 512 * 4 / 128;       // 65536 lines
        for (size_t i = g; i < n1; i += NTH) {
            pf_l2((const char*)word_Wih + i * 128);
            pf_l2((const char*)word_Whh + i * 128);
        }
        // region 2: decoder matrix (102.4 MB)
        const size_t n3 = (size_t)VOC * HW * 4 / 128;             // 819200 lines
        for (size_t i = g; i < n3; i += NTH) {
            if (*(volatile unsigned*)&g_done - base >= (unsigned)NBC) return;
            pf_l2((const char*)dec_W + i * 128);
        }
        return;
    }

    // ---------------- compute CTAs (0..63) ----------------
    const int lane  = threadIdx.x & 31;
    const int wid   = threadIdx.x >> 5;
    const int gw    = blockIdx.x * (NT1 / 32) + wid;   // 0..511
    const int layer = (gw >= HC) ? 1 : 0;
    const int j     = layer ? (gw - HC) : gw;

    __shared__ int sx[LCH];
    if (threadIdx.x < LCH) sx[threadIdx.x] = x_char[threadIdx.x];
    __syncthreads();

    // register-resident char weights for (element j, layer)
    float4 wi[4][2], wh[4][2];
    float  bias[4];
#pragma unroll
    for (int q = 0; q < 4; q++) {
        const int row = layer * (4 * HC) + q * HC + j;
        const float4* pi = (const float4*)(char_Wih + (size_t)row * HC);
        const float4* ph = (const float4*)(char_Whh + (size_t)row * HC);
#pragma unroll
        for (int u = 0; u < 2; u++) {
            wi[q][u] = pi[lane + 32 * u];
            wh[q][u] = ph[lane + 32 * u];
        }
        bias[q] = char_bih[row] + char_bhh[row];
    }
    float c = h_char_c[layer * HC + j];
    if (lane == 0) {
        const float h0v = h_char_h[layer * HC + j];
        if (layer == 0) __stcg(&g_h0[0][j], h0v);
        else            __stcg(&g_h1[0][j], h0v);
    }
    gbar();

    // pipelined char phases: phase p = layer0 step p  ||  layer1 step p-1
#pragma unroll 1
    for (int p = 0; p <= LCH; p++) {
        if (layer == 0) {
            if (p < LCH) {
                const float4* xe = (const float4*)(char_emb + (size_t)sx[p] * HC);
                const float4* hb = (const float4*)g_h0[p & 1];
                const float4 x0 = xe[lane],          x1 = xe[lane + 32];
                const float4 h0 = __ldcg(hb + lane), h1 = __ldcg(hb + lane + 32);
                float acc[4];
#pragma unroll
                for (int q = 0; q < 4; q++) {
                    float a = dot4(wi[q][0], x0) + dot4(wi[q][1], x1)
                            + dot4(wh[q][0], h0) + dot4(wh[q][1], h1);
                    acc[q] = warp_sum(a) + bias[q];
                }
                const float ig = fsig(acc[0]), fg = fsig(acc[1]);
                const float gg = ftanh(acc[2]), og = fsig(acc[3]);
                c = fg * c + ig * gg;
                const float h = og * ftanh(c);
                if (lane == 0) {
                    __stcg(&g_h0[(p + 1) & 1][j], h);
                    if (p == LCH - 1) { out[OUT_CH + j] = h; out[OUT_CC + j] = c; }
                }
            }
        } else {
            if (p >= 1) {
                const float4* xb = (const float4*)g_h0[p & 1];
                const float4* hb = (const float4*)g_h1[(p - 1) & 1];
                const float4 x0 = __ldcg(xb + lane), x1 = __ldcg(xb + lane + 32);
                const float4 h0 = __ldcg(hb + lane), h1 = __ldcg(hb + lane + 32);
                float acc[4];
#pragma unroll
                for (int q = 0; q < 4; q++) {
                    float a = dot4(wi[q][0], x0) + dot4(wi[q][1], x1)
                            + dot4(wh[q][0], h0) + dot4(wh[q][1], h1);
                    acc[q] = warp_sum(a) + bias[q];
                }
                const float ig = fsig(acc[0]), fg = fsig(acc[1]);
                const float gg = ftanh(acc[2]), og = fsig(acc[3]);
                c = fg * c + ig * gg;
                const float h = og * ftanh(c);
                if (lane == 0) {
                    __stcg(&g_h1[p & 1][j], h);
                    if (p == LCH) {
                        __stcg(&g_c1[j], c);
                        out[OUT_CH + HC + j] = h;
                        out[OUT_CC + HC + j] = c;
                    }
                }
            }
        }
        gbar();
    }

    // xc = c2e @ c1 (warp gw -> row gw), warp 0 also computes gate
    {
        const float4* pr  = (const float4*)(c2e + (size_t)gw * HC);
        const float4* c1b = (const float4*)g_c1;
        float a = dot4(pr[lane],      __ldcg(c1b + lane))
                + dot4(pr[lane + 32], __ldcg(c1b + lane + 32));
        a = warp_sum(a);
        if (lane == 0) __stcg(&g_xc[gw], a);

        if (gw == 0) {
            const int widx = x_word[0];
            const float4* we = (const float4*)(word_emb + (size_t)widx * HW);
            const float4* gp = (const float4*)gw_vec;
            float s = 0.f;
#pragma unroll
            for (int u = 0; u < 4; u++) s += dot4(gp[lane + 32 * u], we[lane + 32 * u]);
            s = warp_sum(s) + gb_scal[0];
            if (lane == 0) __stcg(&g_gate, fmaxf(s, 0.f));
        }
    }
    gbar();

    // ---------------- word LSTM layer 0 (warp gw -> element gw) ----------------
    const int e = gw;
    {
        const float gv   = __ldcg(&g_gate);
        const int   widx = x_word[0];
        const float4* we = (const float4*)(word_emb + (size_t)widx * HW);
        const float4* xc = (const float4*)g_xc;
        const float4* hb = (const float4*)h_word_h;
        float4 xv[4], hv[4];
#pragma unroll
        for (int u = 0; u < 4; u++) {
            const float4 a = we[lane + 32 * u];
            const float4 b = __ldcg(xc + lane + 32 * u);
            xv[u] = make_float4((1.f - gv) * a.x + gv * b.x,
                                (1.f - gv) * a.y + gv * b.y,
                                (1.f - gv) * a.z + gv * b.z,
                                (1.f - gv) * a.w + gv * b.w);
            hv[u] = hb[lane + 32 * u];
        }
        float acc[4];
#pragma unroll
        for (int q = 0; q < 4; q++) {
            const int row = q * HW + e;
            const float4* pwi = (const float4*)(word_Wih + (size_t)row * HW);
            const float4* pwh = (const float4*)(word_Whh + (size_t)row * HW);
            float a = 0.f;
#pragma unroll
            for (int u = 0; u < 4; u++) {
                a += dot4(__ldcg(pwi + lane + 32 * u), xv[u]);
                a += dot4(__ldcg(pwh + lane + 32 * u), hv[u]);
            }
            acc[q] = warp_sum(a) + word_bih[row] + word_bhh[row];
        }
        const float ig = fsig(acc[0]), fg = fsig(acc[1]);
        const float gg = ftanh(acc[2]), og = fsig(acc[3]);
        const float cw = fg * h_word_c[e] + ig * gg;
        const float hw = og * ftanh(cw);
        if (lane == 0) {
            __stcg(&g_wh[e], hw);
            out[OUT_WH + e] = hw;
            out[OUT_WC + e] = cw;
        }
    }
    gbar();

    // ---------------- word LSTM layer 1 ----------------
    {
        const float4* xb = (const float4*)g_wh;
        const float4* hb = (const float4*)(h_word_h + HW);
        float4 xv[4], hv[4];
#pragma unroll
        for (int u = 0; u < 4; u++) {
            xv[u] = __ldcg(xb + lane + 32 * u);
            hv[u] = hb[lane + 32 * u];
        }
        float acc[4];
#pragma unroll
        for (int q = 0; q < 4; q++) {
            const int row = 4 * HW + q * HW + e;
            const float4* pwi = (const float4*)(word_Wih + (size_t)row * HW);
            const float4* pwh = (const float4*)(word_Whh + (size_t)row * HW);
            float a = 0.f;
#pragma unroll
            for (int u = 0; u < 4; u++) {
                a += dot4(__ldcg(pwi + lane + 32 * u), xv[u]);
                a += dot4(__ldcg(pwh + lane + 32 * u), hv[u]);
            }
            acc[q] = warp_sum(a) + word_bih[row] + word_bhh[row];
        }
        const float ig = fsig(acc[0]), fg = fsig(acc[1]);
        const float gg = ftanh(acc[2]), og = fsig(acc[3]);
        const float cw = fg * h_word_c[HW + e] + ig * gg;
        const float hw = og * ftanh(cw);
        if (lane == 0) {
            __stcg(&g_y[e], hw);
            out[OUT_WH + HW + e] = hw;
            out[OUT_WC + HW + e] = cw;
        }
    }
    __syncthreads();
    if (threadIdx.x == 0) atomicAdd(&g_done, 1u);   // signal prefetchers to wind down
}

// ============ decoder GEMV (50000 x 512), 2 rows/warp ============
__global__ void __launch_bounds__(NTD) k_dec(const float* __restrict__ dec_W,
                                             const float* __restrict__ dec_b,
                                             float* __restrict__ out)
{
    __shared__ float ys[HW];
    for (int i = threadIdx.x; i < HW; i += NTD) ys[i] = __ldcg(&g_y[i]);
    __syncthreads();

    const int lane = threadIdx.x & 31;
    const int wid  = threadIdx.x >> 5;
    const int gw   = blockIdx.x * (NTD / 32) + wid;
    const int r0   = 2 * gw;

    const float4* y4 = (const float4*)ys;
    float4 yv[4];
#pragma unroll
    for (int u = 0; u < 4; u++) yv[u] = y4[lane + 32 * u];

    const float4* w0 = (const float4*)(dec_W + (size_t)r0 * HW);
    const float4* w1 = w0 + HW / 4;
    float a0 = 0.f, a1 = 0.f;
#pragma unroll
    for (int u = 0; u < 4; u++) {
        const float4 v0 = __ldcg(w0 + lane + 32 * u);
        const float4 v1 = __ldcg(w1 + lane + 32 * u);
        a0 += dot4(v0, yv[u]);
        a1 += dot4(v1, yv[u]);
    }
    a0 = warp_sum(a0);
    a1 = warp_sum(a1);
    if (lane == 0) {
        out[r0]     = a0 + dec_b[r0];
        out[r0 + 1] = a1 + dec_b[r0 + 1];
    }
}

// ---------------- launch ----------------
extern "C" void kernel_launch(void* const* d_in, const int* in_sizes, int n_in,
                              void* d_out, int out_size)
{
    (void)in_sizes; (void)n_in; (void)out_size;
    const int*   x_word   = (const int*)  d_in[0];
    const int*   x_char   = (const int*)  d_in[1];
    const float* h_word_h = (const float*)d_in[2];
    const float* h_word_c = (const float*)d_in[3];
    const float* h_char_h = (const float*)d_in[4];
    const float* h_char_c = (const float*)d_in[5];
    const float* word_emb = (const float*)d_in[6];
    const float* word_Wih = (const float*)d_in[7];
    const float* word_Whh = (const float*)d_in[8];
    const float* word_bih = (const float*)d_in[9];
    const float* word_bhh = (const float*)d_in[10];
    const float* dec_W    = (const float*)d_in[11];
    const float* dec_b    = (const float*)d_in[12];
    const float* char_emb = (const float*)d_in[13];
    const float* char_Wih = (const float*)d_in[14];
    const float* char_Whh = (const float*)d_in[15];
    const float* char_bih = (const float*)d_in[16];
    const float* char_bhh = (const float*)d_in[17];
    const float* c2e      = (const float*)d_in[18];
    const float* g_w      = (const float*)d_in[19];
    const float* g_b      = (const float*)d_in[20];
    float* out = (float*)d_out;

    k_fused<<<NBF, NT1>>>(x_word, x_char, h_word_h, h_word_c, h_char_h, h_char_c,
                          word_emb, word_Wih, word_Whh, word_bih, word_bhh,
                          char_emb, char_Wih, char_Whh, char_bih, char_bhh,
                          c2e, g_w, g_b, dec_W, out);
    k_dec<<<NBD, NTD>>>(dec_W, dec_b, out);
}

// round 4
// speedup vs baseline: 1.6433x; 1.1202x over previous
#include <cuda_runtime.h>
#include <math.h>
#include <stdint.h>

// ---------------- constants ----------------
#define NBF   148         // fused kernel blocks (1/SM, all co-resident)
#define NBC   64          // compute CTAs (512 warps)
#define NAUX  (NBF - NBC) // 84 aux CTAs: gate + h-partials + L2 prefetch
#define NT1   256
#define NBD   3125        // decoder: 3125 blocks * 4 warps * 4 rows = 50000
#define NTD   128

#define HC    256
#define HW    512
#define VOC   50000
#define LCH   12

// d_out layout: [y(50000) | h_word_h(1024) | h_word_c(1024) | h_char_h(512) | h_char_c(512)]
#define OUT_WH  50000
#define OUT_WC  51024
#define OUT_CH  52048
#define OUT_CC  52560

// ---------------- dataflow flags (each on its own 128B line) ----------------
#define F_H0    0              // +p, p=0..12 : char layer0 state p complete (256 sigs)
#define F_H1    13             // +p, p=0..12 : char layer1 state p complete (256 sigs)
#define F_XC    26             // xc rows done (512)
#define F_GATE  27             // gate done (1)
#define F_HP    28             // word h-partial rows done (4096)
#define F_W0    29             // word layer0 elements done (512)
#define F_W1    30             // word layer1 elements done (512)
#define NFLAGS  32
__device__ unsigned g_flags[NFLAGS * 32];   // stride 32 words = 128B per flag

// ---------------- device-global scratch ----------------
__device__ float g_h0[4][HC];     // char layer0 state ring (state p -> buf p&3)
__device__ float g_h1[4][HC];     // char layer1 state ring
__device__ float g_c1[HC];        // final layer1 cell
__device__ float g_xc[HW];
__device__ float g_gate;
__device__ float g_hp[2 * 2048];  // word Whh@h + bias partials (layer0: 0..2047, layer1: 2048..4095)
__device__ float g_wh[HW];
__device__ float g_y[HW];

// ---------------- helpers ----------------
__device__ __forceinline__ void sig(int idx) {
    asm volatile("red.release.gpu.add.u32 [%0], %1;"
                 :: "l"(&g_flags[idx * 32]), "r"(1u) : "memory");
}
__device__ __forceinline__ unsigned ldacq(int idx) {
    unsigned v;
    asm volatile("ld.acquire.gpu.u32 %0, [%1];"
                 : "=r"(v) : "l"(&g_flags[idx * 32]) : "memory");
    return v;
}
__device__ __forceinline__ void waitf(int idx, unsigned tgt) {
    while (ldacq(idx) < tgt) { }
}
__device__ __forceinline__ float warp_sum(float v) {
#pragma unroll
    for (int o = 16; o > 0; o >>= 1) v += __shfl_xor_sync(0xffffffffu, v, o);
    return v;
}
__device__ __forceinline__ float fsig(float x)  { return __fdividef(1.f, 1.f + __expf(-x)); }
__device__ __forceinline__ float ftanh(float x) { float e = __expf(2.f * x); return 1.f - __fdividef(2.f, e + 1.f); }
__device__ __forceinline__ float dot4(float4 a, float4 b) {
    return a.x * b.x + a.y * b.y + a.z * b.z + a.w * b.w;
}
__device__ __forceinline__ void pf_l2(const void* p) {
    asm volatile("prefetch.global.L2 [%0];" :: "l"(p));
}

// ============ fused kernel ============
__global__ void __launch_bounds__(NT1, 1) k_fused(
    const int*   x_word,   const int*   x_char,
    const float* h_word_h, const float* h_word_c,
    const float* h_char_h, const float* h_char_c,
    const float* word_emb, const float* word_Wih, const float* word_Whh,
    const float* word_bih, const float* word_bhh,
    const float* char_emb, const float* char_Wih, const float* char_Whh,
    const float* char_bih, const float* char_bhh,
    const float* c2e,      const float* gw_vec,   const float* gb_scal,
    const float* dec_W,
    float* out)
{
    const int lane = threadIdx.x & 31;
    const int wid  = threadIdx.x >> 5;

    // ================= aux CTAs =================
    if (blockIdx.x >= NBC) {
        const int ab = blockIdx.x - NBC;          // 0..83

        // gate (independent of everything else): aux CTA 0, warp 0
        if (ab == 0 && wid == 0) {
            const int widx = x_word[0];
            const float4* we = (const float4*)(word_emb + (size_t)widx * HW);
            const float4* gp = (const float4*)gw_vec;
            float s = 0.f;
#pragma unroll
            for (int u = 0; u < 4; u++) s += dot4(gp[lane + 32 * u], we[lane + 32 * u]);
            s = warp_sum(s) + gb_scal[0];
            if (lane == 0) { __stcg(&g_gate, fmaxf(s, 0.f)); sig(F_GATE); }
        }

        // word h-partials: hp[r] = Whh_row(r) . h_prev + bih[r] + bhh[r], r = 0..4095
        const int awarp = ab * (NT1 / 32) + wid;  // 0..671
        for (int r = awarp; r < 4096; r += NAUX * (NT1 / 32)) {
            const int l = r >> 11;
            const float4* w  = (const float4*)(word_Whh + (size_t)r * HW);
            const float4* hv = (const float4*)(h_word_h + l * HW);
            float a = 0.f;
#pragma unroll
            for (int u = 0; u < 4; u++) a += dot4(w[lane + 32 * u], hv[lane + 32 * u]);
            a = warp_sum(a);
            if (lane == 0) {
                __stcg(&g_hp[r], a + word_bih[r] + word_bhh[r]);
                sig(F_HP);
            }
        }

        // L2 prefetch: word_Wih (8MB, needed soon) then dec_W (102MB, for k_dec)
        const int g   = ab * NT1 + threadIdx.x;   // 0..21503
        const int NTH = NAUX * NT1;
        const size_t nWih = (size_t)4096 * HW * 4 / 128;
        for (size_t i = g; i < nWih; i += NTH)
            pf_l2((const char*)word_Wih + i * 128);
        const size_t nD = (size_t)VOC * HW * 4 / 128;
        size_t k = 0;
        for (size_t i = g; i < nD; i += NTH, k++) {
            if ((k & 7) == 0 && ldacq(F_W1) >= HW) return;  // compute finished: exit now
            pf_l2((const char*)dec_W + i * 128);
        }
        return;
    }

    // ================= compute CTAs (0..63) =================
    const int gw    = blockIdx.x * (NT1 / 32) + wid;   // 0..511
    const int layer = (gw >= HC) ? 1 : 0;
    const int j     = layer ? (gw - HC) : gw;

    __shared__ int sx[LCH];
    if (threadIdx.x < LCH) sx[threadIdx.x] = x_char[threadIdx.x];
    __syncthreads();

    // register-resident char weights for (element j, layer)
    float4 wi[4][2], wh[4][2];
    float  bias[4];
#pragma unroll
    for (int q = 0; q < 4; q++) {
        const int row = layer * (4 * HC) + q * HC + j;
        const float4* pi = (const float4*)(char_Wih + (size_t)row * HC);
        const float4* ph = (const float4*)(char_Whh + (size_t)row * HC);
#pragma unroll
        for (int u = 0; u < 2; u++) {
            wi[q][u] = pi[lane + 32 * u];
            wh[q][u] = ph[lane + 32 * u];
        }
        bias[q] = char_bih[row] + char_bhh[row];
    }
    float c = h_char_c[layer * HC + j];

    // seed state 0
    if (lane == 0) {
        const float h0v = h_char_h[layer * HC + j];
        if (layer == 0) { __stcg(&g_h0[0][j], h0v); sig(F_H0 + 0); }
        else            { __stcg(&g_h1[0][j], h0v); sig(F_H1 + 0); }
    }

    // ---------------- char recurrence (dataflow) ----------------
    if (layer == 0) {
#pragma unroll 1
        for (int t = 0; t < LCH; t++) {
            waitf(F_H0 + t, HC);
            if (t >= 4) waitf(F_H1 + (t - 3), HC);   // WAR guard on h0 ring (depth 4)
            const float4* xe = (const float4*)(char_emb + (size_t)sx[t] * HC);
            const float4* hb = (const float4*)g_h0[t & 3];
            const float4 x0 = xe[lane],                 x1 = xe[lane + 32];
            const float4 h0 = __ldcg(hb + lane),        h1 = __ldcg(hb + lane + 32);
            float acc[4];
#pragma unroll
            for (int q = 0; q < 4; q++) {
                float a = dot4(wi[q][0], x0) + dot4(wi[q][1], x1)
                        + dot4(wh[q][0], h0) + dot4(wh[q][1], h1);
                acc[q] = warp_sum(a) + bias[q];
            }
            const float ig = fsig(acc[0]), fg = fsig(acc[1]);
            const float gg = ftanh(acc[2]), og = fsig(acc[3]);
            c = fg * c + ig * gg;
            const float h = og * ftanh(c);
            if (lane == 0) {
                __stcg(&g_h0[(t + 1) & 3][j], h);
                if (t == LCH - 1) { out[OUT_CH + j] = h; out[OUT_CC + j] = c; }
                sig(F_H0 + t + 1);
            }
        }
    } else {
#pragma unroll 1
        for (int t = 0; t < LCH; t++) {
            waitf(F_H0 + t + 1, HC);     // x input: layer0 state t+1
            waitf(F_H1 + t, HC);         // own state t
            const float4* xb = (const float4*)g_h0[(t + 1) & 3];
            const float4* hb = (const float4*)g_h1[t & 3];
            const float4 x0 = __ldcg(xb + lane), x1 = __ldcg(xb + lane + 32);
            const float4 h0 = __ldcg(hb + lane), h1 = __ldcg(hb + lane + 32);
            float acc[4];
#pragma unroll
            for (int q = 0; q < 4; q++) {
                float a = dot4(wi[q][0], x0) + dot4(wi[q][1], x1)
                        + dot4(wh[q][0], h0) + dot4(wh[q][1], h1);
                acc[q] = warp_sum(a) + bias[q];
            }
            const float ig = fsig(acc[0]), fg = fsig(acc[1]);
            const float gg = ftanh(acc[2]), og = fsig(acc[3]);
            c = fg * c + ig * gg;
            const float h = og * ftanh(c);
            if (lane == 0) {
                __stcg(&g_h1[(t + 1) & 3][j], h);
                if (t == LCH - 1) {
                    __stcg(&g_c1[j], c);
                    out[OUT_CH + HC + j] = h;
                    out[OUT_CC + HC + j] = c;
                }
                sig(F_H1 + t + 1);
            }
        }
    }

    // ---------------- xc = c2e @ c1 (warp gw -> row gw) ----------------
    {
        waitf(F_H1 + LCH, HC);
        const float4* pr  = (const float4*)(c2e + (size_t)gw * HC);
        const float4* c1b = (const float4*)g_c1;
        float a = dot4(pr[lane],      __ldcg(c1b + lane))
                + dot4(pr[lane + 32], __ldcg(c1b + lane + 32));
        a = warp_sum(a);
        if (lane == 0) { __stcg(&g_xc[gw], a); sig(F_XC); }
    }

    // ---------------- word LSTM layer 0 (warp gw -> element gw) ----------------
    const int e = gw;
    {
        waitf(F_XC, HW);
        waitf(F_GATE, 1);
        waitf(F_HP, 4096);
        const float gv   = __ldcg(&g_gate);
        const int   widx = x_word[0];
        const float4* we = (const float4*)(word_emb + (size_t)widx * HW);
        const float4* xc = (const float4*)g_xc;
        float4 xv[4];
#pragma unroll
        for (int u = 0; u < 4; u++) {
            const float4 a = we[lane + 32 * u];
            const float4 b = __ldcg(xc + lane + 32 * u);
            xv[u] = make_float4((1.f - gv) * a.x + gv * b.x,
                                (1.f - gv) * a.y + gv * b.y,
                                (1.f - gv) * a.z + gv * b.z,
                                (1.f - gv) * a.w + gv * b.w);
        }
        float acc[4];
#pragma unroll
        for (int q = 0; q < 4; q++) {
            const int row = q * HW + e;
            const float4* pwi = (const float4*)(word_Wih + (size_t)row * HW);
            float a = 0.f;
#pragma unroll
            for (int u = 0; u < 4; u++) a += dot4(__ldcg(pwi + lane + 32 * u), xv[u]);
            acc[q] = warp_sum(a) + __ldcg(&g_hp[row]);
        }
        const float ig = fsig(acc[0]), fg = fsig(acc[1]);
        const float gg = ftanh(acc[2]), og = fsig(acc[3]);
        const float cw = fg * h_word_c[e] + ig * gg;
        const float hw = og * ftanh(cw);
        if (lane == 0) {
            __stcg(&g_wh[e], hw);
            out[OUT_WH + e] = hw;
            out[OUT_WC + e] = cw;
            sig(F_W0);
        }
    }

    // ---------------- word LSTM layer 1 ----------------
    {
        waitf(F_W0, HW);
        const float4* xb = (const float4*)g_wh;
        float4 xv[4];
#pragma unroll
        for (int u = 0; u < 4; u++) xv[u] = __ldcg(xb + lane + 32 * u);
        float acc[4];
#pragma unroll
        for (int q = 0; q < 4; q++) {
            const int row = 4 * HW + q * HW + e;   // global row in flat (2,2048,512)
            const float4* pwi = (const float4*)(word_Wih + (size_t)row * HW);
            float a = 0.f;
#pragma unroll
            for (int u = 0; u < 4; u++) a += dot4(__ldcg(pwi + lane + 32 * u), xv[u]);
            acc[q] = warp_sum(a) + __ldcg(&g_hp[2048 + q * HW + e]);
        }
        const float ig = fsig(acc[0]), fg = fsig(acc[1]);
        const float gg = ftanh(acc[2]), og = fsig(acc[3]);
        const float cw = fg * h_word_c[HW + e] + ig * gg;
        const float hw = og * ftanh(cw);
        if (lane == 0) {
            __stcg(&g_y[e], hw);
            out[OUT_WH + HW + e] = hw;
            out[OUT_WC + HW + e] = cw;
            sig(F_W1);
        }
    }
}

// ============ decoder GEMV (50000 x 512), 4 rows/warp ============
__global__ void __launch_bounds__(NTD) k_dec(const float* __restrict__ dec_W,
                                             const float* __restrict__ dec_b,
                                             float* __restrict__ out)
{
    // reset dataflow flags for the NEXT invocation (k_fused of this one is done)
    if (blockIdx.x == 0) {
        for (int i = threadIdx.x; i < NFLAGS * 32; i += NTD) g_flags[i] = 0;
    }

    __shared__ float ys[HW];
    for (int i = threadIdx.x; i < HW; i += NTD) ys[i] = __ldcg(&g_y[i]);
    __syncthreads();

    const int lane = threadIdx.x & 31;
    const int wid  = threadIdx.x >> 5;
    const int gw   = blockIdx.x * (NTD / 32) + wid;
    const int r0   = 4 * gw;                       // exact cover: 12500 warps * 4 rows

    const float4* y4 = (const float4*)ys;
    float4 yv[4];
#pragma unroll
    for (int u = 0; u < 4; u++) yv[u] = y4[lane + 32 * u];

    const float4* wp = (const float4*)(dec_W + (size_t)r0 * HW);
    float4 v[4][4];
#pragma unroll
    for (int k = 0; k < 4; k++)
#pragma unroll
        for (int u = 0; u < 4; u++)
            v[k][u] = __ldcg(wp + (size_t)k * (HW / 4) + lane + 32 * u);

    float a[4];
#pragma unroll
    for (int k = 0; k < 4; k++) {
        float s = 0.f;
#pragma unroll
        for (int u = 0; u < 4; u++) s += dot4(v[k][u], yv[u]);
        a[k] = warp_sum(s);
    }
    if (lane == 0) {
#pragma unroll
        for (int k = 0; k < 4; k++) out[r0 + k] = a[k] + dec_b[r0 + k];
    }
}

// ---------------- launch ----------------
extern "C" void kernel_launch(void* const* d_in, const int* in_sizes, int n_in,
                              void* d_out, int out_size)
{
    (void)in_sizes; (void)n_in; (void)out_size;
    const int*   x_word   = (const int*)  d_in[0];
    const int*   x_char   = (const int*)  d_in[1];
    const float* h_word_h = (const float*)d_in[2];
    const float* h_word_c = (const float*)d_in[3];
    const float* h_char_h = (const float*)d_in[4];
    const float* h_char_c = (const float*)d_in[5];
    const float* word_emb = (const float*)d_in[6];
    const float* word_Wih = (const float*)d_in[7];
    const float* word_Whh = (const float*)d_in[8];
    const float* word_bih = (const float*)d_in[9];
    const float* word_bhh = (const float*)d_in[10];
    const float* dec_W    = (const float*)d_in[11];
    const float* dec_b    = (const float*)d_in[12];
    const float* char_emb = (const float*)d_in[13];
    const float* char_Wih = (const float*)d_in[14];
    const float* char_Whh = (const float*)d_in[15];
    const float* char_bih = (const float*)d_in[16];
    const float* char_bhh = (const float*)d_in[17];
    const float* c2e      = (const float*)d_in[18];
    const float* g_w      = (const float*)d_in[19];
    const float* g_b      = (const float*)d_in[20];
    float* out = (float*)d_out;

    k_fused<<<NBF, NT1>>>(x_word, x_char, h_word_h, h_word_c, h_char_h, h_char_c,
                          word_emb, word_Wih, word_Whh, word_bih, word_bhh,
                          char_emb, char_Wih, char_Whh, char_bih, char_bhh,
                          c2e, g_w, g_b, dec_W, out);
    k_dec<<<NBD, NTD>>>(dec_W, dec_b, out);
}

// round 5
// speedup vs baseline: 1.7107x; 1.0410x over previous
#include <cuda_runtime.h>
#include <math.h>
#include <stdint.h>

// ---------------- constants ----------------
#define NBF   148         // fused kernel blocks (1/SM, all co-resident)
#define NBC   64          // compute CTAs (512 warps)
#define NAUX  (NBF - NBC) // 84 aux CTAs
#define NT1   256
#define NBD   3125        // decoder: 3125 blocks * 8 warps * 2 rows = 50000
#define NTD   256

#define HC    256
#define HW    512
#define VOC   50000
#define LCH   12

// d_out layout: [y(50000) | h_word_h(1024) | h_word_c(1024) | h_char_h(512) | h_char_c(512)]
#define OUT_WH  50000
#define OUT_WC  51024
#define OUT_CH  52048
#define OUT_CC  52560

// ---------------- dataflow flags (one 128B line each) ----------------
#define F_H0    0     // +p : char layer0 state p complete (256 sigs each)
#define F_H1    13    // +p : char layer1 state p complete
#define F_PX    26    // +t : layer0 x-partials for step t done (1024 sigs each)
#define F_XC    38    // xc rows done (512)
#define F_GATE  39    // gate done (1)
#define F_HP0   40    // word layer0 h-partials done (2048)
#define F_HP1   41    // word layer1 h-partials done (2048)
#define F_WIHE  42    // Wih_l0 . word_emb rows done (2048)
#define F_W0    43    // word layer0 elements done (512)
#define F_W1    44    // word layer1 elements done (512)
#define NFLAGS  45
__device__ unsigned g_flags[NFLAGS * 32];

// ---------------- device-global scratch ----------------
__device__ float g_h0[4][HC];         // char layer0 state ring
__device__ float g_h1[4][HC];         // char layer1 state ring
__device__ float g_c1[HC];
__device__ float g_px[LCH * 1024];    // layer0: Wih@x_t + biases
__device__ float g_xc[HW];
__device__ float g_gate;
__device__ float g_wihe[2048];        // word l0: Wih@word_emb[widx]
__device__ float g_hp[2 * 2048];      // word: Whh@h_prev + biases
__device__ float g_wh[HW];
__device__ float g_y[HW];
__device__ float g_sink;

// ---------------- helpers ----------------
__device__ __forceinline__ void sig(int idx) {
    asm volatile("red.release.gpu.add.u32 [%0], %1;"
                 :: "l"(&g_flags[idx * 32]), "r"(1u) : "memory");
}
__device__ __forceinline__ unsigned ldacq(int idx) {
    unsigned v;
    asm volatile("ld.acquire.gpu.u32 %0, [%1];"
                 : "=r"(v) : "l"(&g_flags[idx * 32]) : "memory");
    return v;
}
__device__ __forceinline__ void waitf(int idx, unsigned tgt) {
    while (ldacq(idx) < tgt) { }
}
__device__ __forceinline__ float warp_sum(float v) {
#pragma unroll
    for (int o = 16; o > 0; o >>= 1) v += __shfl_xor_sync(0xffffffffu, v, o);
    return v;
}
__device__ __forceinline__ float fsig(float x)  { return __fdividef(1.f, 1.f + __expf(-x)); }
__device__ __forceinline__ float ftanh(float x) { float e = __expf(2.f * x); return 1.f - __fdividef(2.f, e + 1.f); }
__device__ __forceinline__ float dot4(float4 a, float4 b) {
    return a.x * b.x + a.y * b.y + a.z * b.z + a.w * b.w;
}

// ============ fused kernel ============
__global__ void __launch_bounds__(NT1, 1) k_fused(
    const int*   x_word,   const int*   x_char,
    const float* h_word_h, const float* h_word_c,
    const float* h_char_h, const float* h_char_c,
    const float* word_emb, const float* word_Wih, const float* word_Whh,
    const float* word_bih, const float* word_bhh,
    const float* char_emb, const float* char_Wih, const float* char_Whh,
    const float* char_bih, const float* char_bhh,
    const float* c2e,      const float* gw_vec,   const float* gb_scal,
    float* out)
{
    const int lane = threadIdx.x & 31;
    const int wid  = threadIdx.x >> 5;

    // ================= aux CTAs: critical-path precomputation =================
    if (blockIdx.x >= NBC) {
        const int ab    = blockIdx.x - NBC;            // 0..83
        const int awarp = ab * (NT1 / 32) + wid;       // 0..671
        const int NWRP  = NAUX * (NT1 / 32);           // 672

        // gate (aux CTA 0, warp 0) — fully independent
        if (ab == 0 && wid == 0) {
            const int widx = x_word[0];
            const float4* we = (const float4*)(word_emb + (size_t)widx * HW);
            const float4* gp = (const float4*)gw_vec;
            float s = 0.f;
#pragma unroll
            for (int u = 0; u < 4; u++) s += dot4(gp[lane + 32 * u], we[lane + 32 * u]);
            s = warp_sum(s) + gb_scal[0];
            if (lane == 0) { __stcg(&g_gate, fmaxf(s, 0.f)); sig(F_GATE); }
        }

        // px[t][gr] = char_Wih_l0[gr] . emb(x_t) + bih + bhh  (12288 rows, t-ordered)
        for (int r = awarp; r < LCH * 1024; r += NWRP) {
            const int t  = r >> 10;
            const int gr = r & 1023;
            const int ci = x_char[t];
            const float4* w  = (const float4*)(char_Wih + (size_t)gr * HC);
            const float4* xe = (const float4*)(char_emb + (size_t)ci * HC);
            float a = dot4(w[lane], xe[lane]) + dot4(w[lane + 32], xe[lane + 32]);
            a = warp_sum(a);
            if (lane == 0) {
                __stcg(&g_px[r], a + char_bih[gr] + char_bhh[gr]);
                sig(F_PX + t);
            }
        }

        // wihe[r] = word_Wih_l0[r] . word_emb[widx]  (2048 rows)
        {
            const int widx = x_word[0];
            const float4* we = (const float4*)(word_emb + (size_t)widx * HW);
            float4 ev[4];
#pragma unroll
            for (int u = 0; u < 4; u++) ev[u] = we[lane + 32 * u];
            for (int r = awarp; r < 2048; r += NWRP) {
                const float4* w = (const float4*)(word_Wih + (size_t)r * HW);
                float a = 0.f;
#pragma unroll
                for (int u = 0; u < 4; u++) a += dot4(w[lane + 32 * u], ev[u]);
                a = warp_sum(a);
                if (lane == 0) { __stcg(&g_wihe[r], a); sig(F_WIHE); }
            }
        }

        // hp[r] = word_Whh[r] . h_prev + bih + bhh  (4096 rows)
        for (int r = awarp; r < 4096; r += NWRP) {
            const int l = r >> 11;
            const float4* w  = (const float4*)(word_Whh + (size_t)r * HW);
            const float4* hv = (const float4*)(h_word_h + l * HW);
            float a = 0.f;
#pragma unroll
            for (int u = 0; u < 4; u++) a += dot4(w[lane + 32 * u], hv[lane + 32 * u]);
            a = warp_sum(a);
            if (lane == 0) {
                __stcg(&g_hp[r], a + word_bih[r] + word_bhh[r]);
                sig((r < 2048) ? F_HP0 : F_HP1);
            }
        }

        // warm word_Wih layer1 (4 MB) into L2 with real loads, then exit
        {
            float s = 0.f;
            const float4* base = (const float4*)(word_Wih + (size_t)2048 * HW);
            const int nv = 2048 * HW / 4;                  // 262144 float4
            for (int i = ab * NT1 + threadIdx.x; i < nv; i += NAUX * NT1) {
                const float4 v = __ldcg(base + i);
                s += v.x + v.w;
            }
            if (s == 1.25e33f) g_sink = s;                 // keep loads alive
        }
        return;
    }

    // ================= compute CTAs (0..63) =================
    const int gw    = blockIdx.x * (NT1 / 32) + wid;   // 0..511
    const int layer = (gw >= HC) ? 1 : 0;
    const int j     = layer ? (gw - HC) : gw;

    float c = h_char_c[layer * HC + j];

    // seed state 0
    if (lane == 0) {
        const float h0v = h_char_h[layer * HC + j];
        if (layer == 0) { __stcg(&g_h0[0][j], h0v); sig(F_H0 + 0); }
        else            { __stcg(&g_h1[0][j], h0v); sig(F_H1 + 0); }
    }

    if (layer == 0) {
        // ---- layer 0: only Whh weights in registers (Wih@x precomputed in px) ----
        float4 wh[4][2];
#pragma unroll
        for (int q = 0; q < 4; q++) {
            const float4* ph = (const float4*)(char_Whh + (size_t)(q * HC + j) * HC);
            wh[q][0] = ph[lane];
            wh[q][1] = ph[lane + 32];
        }
#pragma unroll 1
        for (int t = 0; t < LCH; t++) {
            waitf(F_PX + t, 1024);
            float px[4];
#pragma unroll
            for (int q = 0; q < 4; q++) px[q] = __ldcg(&g_px[t * 1024 + q * HC + j]);
            waitf(F_H0 + t, HC);
            if (t >= 4) waitf(F_H1 + (t - 3), HC);          // WAR guard on ring
            const float4* hb = (const float4*)g_h0[t & 3];
            const float4 h0 = __ldcg(hb + lane), h1 = __ldcg(hb + lane + 32);
            float acc[4];
#pragma unroll
            for (int q = 0; q < 4; q++)
                acc[q] = warp_sum(dot4(wh[q][0], h0) + dot4(wh[q][1], h1)) + px[q];
            const float ig = fsig(acc[0]), fg = fsig(acc[1]);
            const float gg = ftanh(acc[2]), og = fsig(acc[3]);
            c = fg * c + ig * gg;
            const float h = og * ftanh(c);
            if (lane == 0) {
                __stcg(&g_h0[(t + 1) & 3][j], h);
                if (t == LCH - 1) { out[OUT_CH + j] = h; out[OUT_CC + j] = c; }
                sig(F_H0 + t + 1);
            }
        }
    } else {
        // ---- layer 1: full Wih+Whh in registers ----
        float4 wi[4][2], wh[4][2];
        float  bias[4];
#pragma unroll
        for (int q = 0; q < 4; q++) {
            const int row = 4 * HC + q * HC + j;
            const float4* pi = (const float4*)(char_Wih + (size_t)row * HC);
            const float4* ph = (const float4*)(char_Whh + (size_t)row * HC);
            wi[q][0] = pi[lane];      wi[q][1] = pi[lane + 32];
            wh[q][0] = ph[lane];      wh[q][1] = ph[lane + 32];
            bias[q]  = char_bih[row] + char_bhh[row];
        }
#pragma unroll 1
        for (int t = 0; t < LCH; t++) {
            waitf(F_H0 + t + 1, HC);     // x input: layer0 state t+1
            waitf(F_H1 + t, HC);         // own state t
            const float4* xb = (const float4*)g_h0[(t + 1) & 3];
            const float4* hb = (const float4*)g_h1[t & 3];
            const float4 x0 = __ldcg(xb + lane), x1 = __ldcg(xb + lane + 32);
            const float4 h0 = __ldcg(hb + lane), h1 = __ldcg(hb + lane + 32);
            float acc[4];
#pragma unroll
            for (int q = 0; q < 4; q++) {
                float a = dot4(wi[q][0], x0) + dot4(wi[q][1], x1)
                        + dot4(wh[q][0], h0) + dot4(wh[q][1], h1);
                acc[q] = warp_sum(a) + bias[q];
            }
            const float ig = fsig(acc[0]), fg = fsig(acc[1]);
            const float gg = ftanh(acc[2]), og = fsig(acc[3]);
            c = fg * c + ig * gg;
            const float h = og * ftanh(c);
            if (lane == 0) {
                __stcg(&g_h1[(t + 1) & 3][j], h);
                if (t == LCH - 1) {
                    __stcg(&g_c1[j], c);
                    out[OUT_CH + HC + j] = h;
                    out[OUT_CC + HC + j] = c;
                }
                sig(F_H1 + t + 1);
            }
        }
    }

    // ---------------- xc = c2e @ c1 (warp gw -> row gw) ----------------
    {
        waitf(F_H1 + LCH, HC);
        const float4* pr  = (const float4*)(c2e + (size_t)gw * HC);
        const float4* c1b = (const float4*)g_c1;
        float a = dot4(pr[lane],      __ldcg(c1b + lane))
                + dot4(pr[lane + 32], __ldcg(c1b + lane + 32));
        a = warp_sum(a);
        if (lane == 0) { __stcg(&g_xc[gw], a); sig(F_XC); }
    }

    // ---------------- word LSTM layer 0 (warp gw -> element gw) ----------------
    const int e = gw;
    {
        waitf(F_XC, HW);
        waitf(F_GATE, 1);
        waitf(F_WIHE, 2048);
        waitf(F_HP0, 2048);
        const float gv = __ldcg(&g_gate);
        const float4* xc = (const float4*)g_xc;
        float4 xv[4];
#pragma unroll
        for (int u = 0; u < 4; u++) xv[u] = __ldcg(xc + lane + 32 * u);
        float acc[4];
#pragma unroll
        for (int q = 0; q < 4; q++) {
            const int row = q * HW + e;
            const float4* pwi = (const float4*)(word_Wih + (size_t)row * HW);
            float a = 0.f;
#pragma unroll
            for (int u = 0; u < 4; u++) a += dot4(__ldcg(pwi + lane + 32 * u), xv[u]);
            acc[q] = gv * warp_sum(a) + (1.f - gv) * __ldcg(&g_wihe[row]) + __ldcg(&g_hp[row]);
        }
        const float ig = fsig(acc[0]), fg = fsig(acc[1]);
        const float gg = ftanh(acc[2]), og = fsig(acc[3]);
        const float cw = fg * h_word_c[e] + ig * gg;
        const float hw = og * ftanh(cw);
        if (lane == 0) {
            __stcg(&g_wh[e], hw);
            out[OUT_WH + e] = hw;
            out[OUT_WC + e] = cw;
            sig(F_W0);
        }
    }

    // ---------------- word LSTM layer 1 ----------------
    {
        waitf(F_HP1, 2048);
        waitf(F_W0, HW);
        const float4* xb = (const float4*)g_wh;
        float4 xv[4];
#pragma unroll
        for (int u = 0; u < 4; u++) xv[u] = __ldcg(xb + lane + 32 * u);
        float acc[4];
#pragma unroll
        for (int q = 0; q < 4; q++) {
            const int row = 2048 + q * HW + e;
            const float4* pwi = (const float4*)(word_Wih + (size_t)row * HW);
            float a = 0.f;
#pragma unroll
            for (int u = 0; u < 4; u++) a += dot4(__ldcg(pwi + lane + 32 * u), xv[u]);
            acc[q] = warp_sum(a) + __ldcg(&g_hp[row]);
        }
        const float ig = fsig(acc[0]), fg = fsig(acc[1]);
        const float gg = ftanh(acc[2]), og = fsig(acc[3]);
        const float cw = fg * h_word_c[HW + e] + ig * gg;
        const float hw = og * ftanh(cw);
        if (lane == 0) {
            __stcg(&g_y[e], hw);
            out[OUT_WH + HW + e] = hw;
            out[OUT_WC + HW + e] = cw;
            sig(F_W1);
        }
    }
}

// ============ decoder GEMV (50000 x 512), 2 rows/warp, streaming loads ============
__global__ void __launch_bounds__(NTD) k_dec(const float* __restrict__ dec_W,
                                             const float* __restrict__ dec_b,
                                             float* __restrict__ out)
{
    // reset dataflow flags for the next graph replay (k_fused already done)
    if (blockIdx.x == 0) {
        for (int i = threadIdx.x; i < NFLAGS * 32; i += NTD) g_flags[i] = 0;
    }

    __shared__ float ys[HW];
    for (int i = threadIdx.x; i < HW; i += NTD) ys[i] = __ldcg(&g_y[i]);
    __syncthreads();

    const int lane = threadIdx.x & 31;
    const int wid  = threadIdx.x >> 5;
    const int gw   = blockIdx.x * (NTD / 32) + wid;
    const int r0   = 2 * gw;                        // 25000 warps * 2 rows

    const float4* y4 = (const float4*)ys;
    float4 yv[4];
#pragma unroll
    for (int u = 0; u < 4; u++) yv[u] = y4[lane + 32 * u];

    const float4* w0 = (const float4*)(dec_W + (size_t)r0 * HW);
    const float4* w1 = w0 + HW / 4;
    float a0 = 0.f, a1 = 0.f;
#pragma unroll
    for (int u = 0; u < 4; u++) {
        const float4 v0 = __ldcs(w0 + lane + 32 * u);   // evict-first: protect L2
        const float4 v1 = __ldcs(w1 + lane + 32 * u);
        a0 += dot4(v0, yv[u]);
        a1 += dot4(v1, yv[u]);
    }
    a0 = warp_sum(a0);
    a1 = warp_sum(a1);
    if (lane == 0) {
        out[r0]     = a0 + dec_b[r0];
        out[r0 + 1] = a1 + dec_b[r0 + 1];
    }
}

// ---------------- launch ----------------
extern "C" void kernel_launch(void* const* d_in, const int* in_sizes, int n_in,
                              void* d_out, int out_size)
{
    (void)in_sizes; (void)n_in; (void)out_size;
    const int*   x_word   = (const int*)  d_in[0];
    const int*   x_char   = (const int*)  d_in[1];
    const float* h_word_h = (const float*)d_in[2];
    const float* h_word_c = (const float*)d_in[3];
    const float* h_char_h = (const float*)d_in[4];
    const float* h_char_c = (const float*)d_in[5];
    const float* word_emb = (const float*)d_in[6];
    const float* word_Wih = (const float*)d_in[7];
    const float* word_Whh = (const float*)d_in[8];
    const float* word_bih = (const float*)d_in[9];
    const float* word_bhh = (const float*)d_in[10];
    const float* dec_W    = (const float*)d_in[11];
    const float* dec_b    = (const float*)d_in[12];
    const float* char_emb = (const float*)d_in[13];
    const float* char_Wih = (const float*)d_in[14];
    const float* char_Whh = (const float*)d_in[15];
    const float* char_bih = (const float*)d_in[16];
    const float* char_bhh = (const float*)d_in[17];
    const float* c2e      = (const float*)d_in[18];
    const float* g_w      = (const float*)d_in[19];
    const float* g_b      = (const float*)d_in[20];
    float* out = (float*)d_out;

    k_fused<<<NBF, NT1>>>(x_word, x_char, h_word_h, h_word_c, h_char_h, h_char_c,
                          word_emb, word_Wih, word_Whh, word_bih, word_bhh,
                          char_emb, char_Wih, char_Whh, char_bih, char_bhh,
                          c2e, g_w, g_b, out);
    k_dec<<<NBD, NTD>>>(dec_W, dec_b, out);
}